// round 11
// baseline (speedup 1.0000x reference)
#include <cuda_runtime.h>
#include <cuda_bf16.h>
#include <cstdint>
#include <math.h>

// ===========================================================================
// Fused MoE: gate(top-2 softmax, fp32) + layer1(+SiLU) + grouped layer2 +
// weighted combine + residual.  bf16 mma.sync.m16n8k16.
// R9: warp tile 16x64 (ldsm:mma ratio 0.625 vs 1.0) + single barrier/stage
// with prefetch-after-barrier.  TM=32, 2 CTAs/SM.
// ===========================================================================

namespace {
constexpr int C    = 256;
constexpr int E    = 4;
constexpr int THW  = 16 * 32 * 32;   // 16384
constexpr int NTOK = 2 * THW;        // 32768
constexpr int TM   = 32;             // tokens per CTA
constexpr int NCTA = NTOK / TM;      // 1024
constexpr int NTHR = 256;            // 8 warps

constexpr int NSTAGE      = 32;      // e*8 + phase (0-3: w1 kq, 4-7: w2 kq)
constexpr int STAGE_BYTES = 32768;   // 256 rows x 64 k x bf16 (swizzled)

// shared memory byte offsets
constexpr int SM_WBUF0 = 0;
constexpr int SM_WBUF1 = 32768;
constexpr int SM_XS    = 65536;            // x bf16 [32][256] swizzled (16 KB)
constexpr int SM_HS    = 81920;            // h bf16 [32][256] swizzled (16 KB)
constexpr int SM_B1    = 98304;            // b1 fp32 [1024]
constexpr int SM_B2    = 102400;           // b2 fp32 [1024]
constexpr int SM_WT    = 106496;           // gate weights [32][4] fp32
constexpr int SM_TOTAL = 107008;           // 104.5 KB -> 2 CTAs/SM
// gating-phase overlays (HS unused then)
constexpr int SM_GW    = SM_HS;            // gate_w fp32 [1024]
constexpr int SM_SP    = SM_HS + 4096;     // logit partials [8][32][4]
}  // namespace

__device__ __align__(16) unsigned char g_wimg[NSTAGE * STAGE_BYTES];

// ------------------------------ helpers -----------------------------------
__device__ __forceinline__ uint32_t smem_u32(const void* p) {
  uint32_t a;
  asm("{ .reg .u64 t; cvta.to.shared.u64 t, %1; cvt.u32.u64 %0, t; }"
      : "=r"(a) : "l"(p));
  return a;
}
__device__ __forceinline__ void ldsm4(uint32_t* r, uint32_t addr) {
  asm volatile("ldmatrix.sync.aligned.m8n8.x4.shared.b16 {%0,%1,%2,%3}, [%4];"
               : "=r"(r[0]), "=r"(r[1]), "=r"(r[2]), "=r"(r[3]) : "r"(addr));
}
__device__ __forceinline__ void mma16816(float* d, const uint32_t* a,
                                         const uint32_t* b) {
  asm volatile(
      "mma.sync.aligned.m16n8k16.row.col.f32.bf16.bf16.f32 "
      "{%0,%1,%2,%3}, {%4,%5,%6,%7}, {%8,%9}, {%0,%1,%2,%3};"
      : "+f"(d[0]), "+f"(d[1]), "+f"(d[2]), "+f"(d[3])
      : "r"(a[0]), "r"(a[1]), "r"(a[2]), "r"(a[3]), "r"(b[0]), "r"(b[1]));
}
__device__ __forceinline__ void cp16(uint32_t dst, const void* src) {
  asm volatile("cp.async.cg.shared.global [%0], [%1], 16;"
               :: "r"(dst), "l"(src));
}
__device__ __forceinline__ void cp_commit() {
  asm volatile("cp.async.commit_group;" ::: "memory");
}
template <int N>
__device__ __forceinline__ void cp_wait() {
  asm volatile("cp.async.wait_group %0;" :: "n"(N) : "memory");
}
__device__ __forceinline__ uint32_t pack_bf2(float a, float b) {
  __nv_bfloat162 t = __floats2bfloat162_rn(a, b);  // .x = a (low)
  return *reinterpret_cast<uint32_t*>(&t);
}

// One 64-k stage: warp tile M=16 (tokens), N=64 (out-channels), K=64.
// A: smem bf16 [32 rows][256 k], 512B rows, swizzle kc^(row&7).
// B: stage buf [256 rows(n)][64 k], 128B rows, same swizzle.
// 20 ldsm4 / 32 MMAs per warp-stage.
__device__ __forceinline__ void run_stage(float (&acc)[8][4],
                                          uint32_t asrc, int kbase,
                                          uint32_t wbuf, int wm, int wn4,
                                          int lane) {
  const int r  = lane & 7;
  const int mi = lane >> 3;
  const uint32_t arow = asrc + (uint32_t)(wm * 16 + (mi & 1) * 8 + r) * 512;
  const uint32_t brow = wbuf + (uint32_t)(wn4 * 64 + r) * 128;
  const int kb8 = kbase >> 3;
#pragma unroll
  for (int kq = 0; kq < 2; ++kq) {
    uint32_t a[2][4];
#pragma unroll
    for (int ks = 0; ks < 2; ++ks) {
      int kc = kb8 + (kq * 2 + ks) * 2 + (mi >> 1);
      ldsm4(a[ks], arow + ((kc ^ r) << 4));
    }
    const int kcb = kq * 4 + mi;
#pragma unroll
    for (int nt = 0; nt < 8; ++nt) {
      uint32_t b[4];
      ldsm4(b, brow + (uint32_t)(nt * 8) * 128 + ((kcb ^ r) << 4));
      mma16816(acc[nt], a[0], b);
      mma16816(acc[nt], a[1], b + 2);
    }
  }
}

// ---------------------------------------------------------------------------
// Prologue: bf16 swizzled weight images (32 stages x 256 rows x 64 k).
// ---------------------------------------------------------------------------
__global__ void prep_weights(const float* __restrict__ w1,
                             const float* __restrict__ w2) {
  int idx = blockIdx.x * blockDim.x + threadIdx.x;  // 65536 threads
  int s  = idx >> 11;          // stage (2048 uint4 per stage)
  int r  = (idx >> 3) & 255;   // row (out/hidden channel)
  int kc = idx & 7;            // 16B chunk within 64-k row
  int e = s >> 3, ph = s & 7;
  const float* src;
  if (ph < 4) src = w1 + (size_t)(e * 256 + r) * 256 + ph * 64 + kc * 8;
  else        src = w2 + (size_t)e * 65536 + (size_t)r * 256 + (ph - 4) * 64 + kc * 8;
  float4 v0 = *reinterpret_cast<const float4*>(src);
  float4 v1 = *reinterpret_cast<const float4*>(src + 4);
  uint4 pk;
  pk.x = pack_bf2(v0.x, v0.y);
  pk.y = pack_bf2(v0.z, v0.w);
  pk.z = pack_bf2(v1.x, v1.y);
  pk.w = pack_bf2(v1.z, v1.w);
  *reinterpret_cast<uint4*>(g_wimg + (size_t)s * STAGE_BYTES + r * 128 +
                            ((kc ^ (r & 7)) << 4)) = pk;
}

// ---------------------------------------------------------------------------
// Main fused kernel.
// ---------------------------------------------------------------------------
__global__ __launch_bounds__(NTHR, 2)
void moe_mma_kernel(const float* __restrict__ x,
                    const float* __restrict__ gate_w,
                    const float* __restrict__ gate_b,
                    const float* __restrict__ b1,
                    const float* __restrict__ b2,
                    float* __restrict__ out) {
  extern __shared__ __align__(16) unsigned char smraw[];
  const uint32_t smb = smem_u32(smraw);
  float* gws  = reinterpret_cast<float*>(smraw + SM_GW);
  float* b1s  = reinterpret_cast<float*>(smraw + SM_B1);
  float* b2s  = reinterpret_cast<float*>(smraw + SM_B2);
  float* sp   = reinterpret_cast<float*>(smraw + SM_SP);
  float* wts  = reinterpret_cast<float*>(smraw + SM_WT);

  const int tid  = threadIdx.x;
  const int lane = tid & 31;
  const int wid  = tid >> 5;
  const int wm   = wid >> 2;   // 0..1: token block (16 rows)
  const int wn4  = wid & 3;    // 0..3: out-col block (64 cols)

  const int token0 = blockIdx.x * TM;
  const int bidx   = token0 / THW;
  const int s0     = token0 % THW;
  const float* xb = x   + (size_t)bidx * C * THW + s0;
  float*       ob = out + (size_t)bidx * C * THW + s0;

  // --- kick stage 0 weight copy immediately -------------------------------
  {
    const unsigned char* src = g_wimg;
#pragma unroll
    for (int it = 0; it < 8; ++it) {
      int off = it * 4096 + tid * 16;
      cp16(smb + SM_WBUF0 + off, src + off);
    }
    cp_commit();
  }

  // --- stage gate_w / b1 / b2 ---------------------------------------------
#pragma unroll
  for (int rr = 0; rr < 4; ++rr) {
    int i = rr * NTHR + tid;
    gws[i] = gate_w[i];
    b1s[i] = b1[i];
    b2s[i] = b2[i];
  }
  __syncthreads();

  // --- x staging (fp32->bf16, swizzled) + fp32 gate logit partials --------
  {
    const int t   = tid & 31;
    const int cpg = tid >> 5;  // 0..7
    float l[4] = {0.f, 0.f, 0.f, 0.f};
    const float* gx = xb + t;
#pragma unroll
    for (int it = 0; it < 16; ++it) {
      int c0 = it * 16 + cpg * 2;
      float v0 = __ldg(gx + (size_t)c0 * THW);
      float v1 = __ldg(gx + (size_t)(c0 + 1) * THW);
#pragma unroll
      for (int e = 0; e < 4; ++e)
        l[e] = fmaf(gws[e * 256 + c0], v0, fmaf(gws[e * 256 + c0 + 1], v1, l[e]));
      uint32_t pk = pack_bf2(v0, v1);
      uint32_t off = t * 512 + (((c0 >> 3) ^ (t & 7)) << 4) + (c0 & 7) * 2;
      *reinterpret_cast<uint32_t*>(smraw + SM_XS + off) = pk;
    }
#pragma unroll
    for (int e = 0; e < 4; ++e) sp[cpg * 128 + t * 4 + e] = l[e];
  }
  __syncthreads();

  // --- logits reduce + top-2 softmax --------------------------------------
  if (tid < 32) {
    float l[4];
#pragma unroll
    for (int e = 0; e < 4; ++e) {
      float s = __ldg(gate_b + e);
#pragma unroll
      for (int g = 0; g < 8; ++g) s += sp[g * 128 + tid * 4 + e];
      l[e] = s;
    }
    float v1 = l[0]; int i1 = 0;
    if (l[1] > v1) { v1 = l[1]; i1 = 1; }
    if (l[2] > v1) { v1 = l[2]; i1 = 2; }
    if (l[3] > v1) { v1 = l[3]; i1 = 3; }
    float v2 = -3.402823e38f; int i2 = 0;
#pragma unroll
    for (int e = 0; e < 4; ++e)
      if (e != i1 && l[e] > v2) { v2 = l[e]; i2 = e; }
    float e2  = __expf(v2 - v1);
    float inv = 1.0f / (1.0f + e2);
    wts[tid * 4 + 0] = 0.f; wts[tid * 4 + 1] = 0.f;
    wts[tid * 4 + 2] = 0.f; wts[tid * 4 + 3] = 0.f;
    wts[tid * 4 + i1] = inv;
    wts[tid * 4 + i2] = e2 * inv;
  }

  // --- main pipelined loop over 32 weight stages --------------------------
  // Per stage: wait data -> ONE barrier -> issue next prefetch -> compute.
  // The barrier both publishes the arrived buffer and proves the prefetch
  // target's readers (previous stage) are done.
  float acc1[8][4], acc2[8][4];
#pragma unroll
  for (int nt = 0; nt < 8; ++nt)
#pragma unroll
    for (int j = 0; j < 4; ++j) acc2[nt][j] = 0.f;

#pragma unroll 1
  for (int s = 0; s < NSTAGE; ++s) {
    cp_wait<0>();
    __syncthreads();

    if (s + 1 < NSTAGE) {  // prefetch next stage; overlaps this stage's math
      const unsigned char* src = g_wimg + (size_t)(s + 1) * STAGE_BYTES;
      uint32_t dst = smb + (((s + 1) & 1) ? SM_WBUF1 : SM_WBUF0);
#pragma unroll
      for (int it = 0; it < 8; ++it) {
        int off = it * 4096 + tid * 16;
        cp16(dst + off, src + off);
      }
      cp_commit();
    }

    const int ph = s & 7, e = s >> 3;
    const uint32_t wbuf = smb + ((s & 1) ? SM_WBUF1 : SM_WBUF0);

    if (ph < 4) {
      if (ph == 0) {
#pragma unroll
        for (int nt = 0; nt < 8; ++nt)
#pragma unroll
          for (int j = 0; j < 4; ++j) acc1[nt][j] = 0.f;
      }
      run_stage(acc1, smb + SM_XS, ph * 64, wbuf, wm, wn4, lane);
      if (ph == 3) {
        // h epilogue: +b1, SiLU, x gate weight, pack bf16 -> hs
        const int tok1 = wm * 16 + (lane >> 2);
        const int tok2 = tok1 + 8;
        const float wt1 = wts[tok1 * 4 + e];
        const float wt2 = wts[tok2 * 4 + e];
#pragma unroll
        for (int nt = 0; nt < 8; ++nt) {
          int n = wn4 * 64 + nt * 8 + (lane & 3) * 2;
          float ba = b1s[e * 256 + n], bb = b1s[e * 256 + n + 1];
          float h0 = acc1[nt][0] + ba, h1 = acc1[nt][1] + bb;
          float h2 = acc1[nt][2] + ba, h3 = acc1[nt][3] + bb;
          h0 = h0 * (1.0f / (1.0f + __expf(-h0))) * wt1;
          h1 = h1 * (1.0f / (1.0f + __expf(-h1))) * wt1;
          h2 = h2 * (1.0f / (1.0f + __expf(-h2))) * wt2;
          h3 = h3 * (1.0f / (1.0f + __expf(-h3))) * wt2;
          uint32_t o1 = tok1 * 512 + (((n >> 3) ^ (tok1 & 7)) << 4) + (n & 7) * 2;
          uint32_t o2 = tok2 * 512 + (((n >> 3) ^ (tok2 & 7)) << 4) + (n & 7) * 2;
          *reinterpret_cast<uint32_t*>(smraw + SM_HS + o1) = pack_bf2(h0, h1);
          *reinterpret_cast<uint32_t*>(smraw + SM_HS + o2) = pack_bf2(h2, h3);
        }
      }
    } else {
      run_stage(acc2, smb + SM_HS, (ph - 4) * 64, wbuf, wm, wn4, lane);
    }
  }
  __syncthreads();  // all warps done reading wbuf before d2s overlay

  // --- final epilogue: acc2 -> smem (coalescing relay) -> global ----------
  float* d2s = reinterpret_cast<float*>(smraw);  // overlays weight buffers
  {
    const int tok1 = wm * 16 + (lane >> 2);
    const int tok2 = tok1 + 8;
#pragma unroll
    for (int nt = 0; nt < 8; ++nt) {
      int n = wn4 * 64 + nt * 8 + (lane & 3) * 2;
      *reinterpret_cast<float2*>(d2s + tok1 * 258 + n) =
          make_float2(acc2[nt][0], acc2[nt][1]);
      *reinterpret_cast<float2*>(d2s + tok2 * 258 + n) =
          make_float2(acc2[nt][2], acc2[nt][3]);
    }
  }
  __syncthreads();
  {
    const int t  = tid & 31;
    const int cg = tid >> 5;   // 0..7
    const float w0 = wts[t * 4 + 0], w1w = wts[t * 4 + 1];
    const float w2w = wts[t * 4 + 2], w3 = wts[t * 4 + 3];
#pragma unroll 4
    for (int i = 0; i < 32; ++i) {
      int ch = i * 8 + cg;
      float v = d2s[t * 258 + ch]
              + w0  * b2s[ch]       + w1w * b2s[256 + ch]
              + w2w * b2s[512 + ch] + w3  * b2s[768 + ch]
              + __ldg(xb + (size_t)ch * THW + t);
      ob[(size_t)ch * THW + t] = v;
    }
  }
}

// ---------------------------------------------------------------------------
extern "C" void kernel_launch(void* const* d_in, const int* in_sizes, int n_in,
                              void* d_out, int out_size) {
  const float* x      = (const float*)d_in[0];
  const float* gate_w = (const float*)d_in[1];
  const float* gate_b = (const float*)d_in[2];
  const float* w1     = (const float*)d_in[3];
  const float* b1     = (const float*)d_in[4];
  const float* w2     = (const float*)d_in[5];
  const float* b2     = (const float*)d_in[6];
  float* out          = (float*)d_out;
  (void)in_sizes; (void)n_in; (void)out_size;

  prep_weights<<<256, 256>>>(w1, w2);

  cudaFuncSetAttribute(moe_mma_kernel,
                       cudaFuncAttributeMaxDynamicSharedMemorySize, SM_TOTAL);
  moe_mma_kernel<<<NCTA, NTHR, SM_TOTAL>>>(x, gate_w, gate_b, b1, b2, out);
}

// round 13
// speedup vs baseline: 1.1624x; 1.1624x over previous
#include <cuda_runtime.h>
#include <cuda_bf16.h>
#include <cstdint>
#include <math.h>

// ===========================================================================
// Fused MoE: gate(top-2 softmax, fp32) + layer1(+SiLU) + grouped layer2 +
// weighted combine + residual.  bf16 mma.sync.m16n8k16.
// R12: R8 structure (32x32 warp tiles, 0.5 ldsm/mma, 2 CTAs/SM) +
// precomputed ldsm addresses (R8 burned ~20% of issue on ALU addr chains).
// ===========================================================================

namespace {
constexpr int C    = 256;
constexpr int E    = 4;
constexpr int THW  = 16 * 32 * 32;   // 16384
constexpr int NTOK = 2 * THW;        // 32768
constexpr int TM   = 32;             // tokens per CTA
constexpr int NCTA = NTOK / TM;      // 1024
constexpr int NTHR = 256;            // 8 warps

constexpr int NSTAGE      = 32;      // e*8 + phase (0-3: w1 kq, 4-7: w2 kq)
constexpr int STAGE_BYTES = 32768;   // 256 rows x 64 k x bf16 (swizzled)

// shared memory byte offsets
constexpr int SM_WBUF0 = 0;
constexpr int SM_WBUF1 = 32768;
constexpr int SM_XS    = 65536;            // x bf16 [32][256] swizzled (16 KB)
constexpr int SM_HS    = 81920;            // h bf16 [32][256] swizzled (16 KB)
constexpr int SM_B1    = 98304;            // b1 fp32 [1024]
constexpr int SM_B2    = 102400;           // b2 fp32 [1024]
constexpr int SM_WT    = 106496;           // gate weights [32][4] fp32
constexpr int SM_TOTAL = 107008;           // 104.5 KB -> 2 CTAs/SM
// gating-phase overlays (HS unused then)
constexpr int SM_GW    = SM_HS;            // gate_w fp32 [1024]
constexpr int SM_SP    = SM_HS + 4096;     // logit partials [8][32][4]
}  // namespace

__device__ __align__(16) unsigned char g_wimg[NSTAGE * STAGE_BYTES];

// ------------------------------ helpers -----------------------------------
__device__ __forceinline__ uint32_t smem_u32(const void* p) {
  uint32_t a;
  asm("{ .reg .u64 t; cvta.to.shared.u64 t, %1; cvt.u32.u64 %0, t; }"
      : "=r"(a) : "l"(p));
  return a;
}
__device__ __forceinline__ void ldsm4(uint32_t* r, uint32_t addr) {
  asm volatile("ldmatrix.sync.aligned.m8n8.x4.shared.b16 {%0,%1,%2,%3}, [%4];"
               : "=r"(r[0]), "=r"(r[1]), "=r"(r[2]), "=r"(r[3]) : "r"(addr));
}
__device__ __forceinline__ void mma16816(float* d, const uint32_t* a,
                                         const uint32_t* b) {
  asm volatile(
      "mma.sync.aligned.m16n8k16.row.col.f32.bf16.bf16.f32 "
      "{%0,%1,%2,%3}, {%4,%5,%6,%7}, {%8,%9}, {%0,%1,%2,%3};"
      : "+f"(d[0]), "+f"(d[1]), "+f"(d[2]), "+f"(d[3])
      : "r"(a[0]), "r"(a[1]), "r"(a[2]), "r"(a[3]), "r"(b[0]), "r"(b[1]));
}
__device__ __forceinline__ void cp16(uint32_t dst, const void* src) {
  asm volatile("cp.async.cg.shared.global [%0], [%1], 16;"
               :: "r"(dst), "l"(src));
}
__device__ __forceinline__ void cp_commit() {
  asm volatile("cp.async.commit_group;" ::: "memory");
}
template <int N>
__device__ __forceinline__ void cp_wait() {
  asm volatile("cp.async.wait_group %0;" :: "n"(N) : "memory");
}
__device__ __forceinline__ uint32_t pack_bf2(float a, float b) {
  __nv_bfloat162 t = __floats2bfloat162_rn(a, b);  // .x = a (low)
  return *reinterpret_cast<uint32_t*>(&t);
}

// One 64-k stage, warp tile M=32 N=32 K=64, with PRECOMPUTED addresses.
// aofs[mt*4 + kq*2 + ks] : A smem address offsets (add asel = hs?16384:0 + ph*128)
// bofs[nt*2 + kq]        : B offsets within stage buffer (add wbuf)
__device__ __forceinline__ void run_stage(float (&acc)[2][4][4],
                                          const uint32_t (&aofs)[8],
                                          uint32_t asel,
                                          const uint32_t (&bofs)[8],
                                          uint32_t wbuf) {
#pragma unroll
  for (int kq = 0; kq < 2; ++kq) {
    uint32_t a[2][2][4];
#pragma unroll
    for (int mt = 0; mt < 2; ++mt)
#pragma unroll
      for (int ks = 0; ks < 2; ++ks)
        ldsm4(a[mt][ks], aofs[mt * 4 + kq * 2 + ks] + asel);
#pragma unroll
    for (int nt = 0; nt < 4; ++nt) {
      uint32_t b[4];
      ldsm4(b, wbuf + bofs[nt * 2 + kq]);
#pragma unroll
      for (int mt = 0; mt < 2; ++mt) {
        mma16816(acc[mt][nt], a[mt][0], b);
        mma16816(acc[mt][nt], a[mt][1], b + 2);
      }
    }
  }
}

// ---------------------------------------------------------------------------
// Prologue: bf16 swizzled weight images (32 stages x 256 rows x 64 k).
// ---------------------------------------------------------------------------
__global__ void prep_weights(const float* __restrict__ w1,
                             const float* __restrict__ w2) {
  int idx = blockIdx.x * blockDim.x + threadIdx.x;  // 65536 threads
  int s  = idx >> 11;          // stage (2048 uint4 per stage)
  int r  = (idx >> 3) & 255;   // row (out/hidden channel)
  int kc = idx & 7;            // 16B chunk within 64-k row
  int e = s >> 3, ph = s & 7;
  const float* src;
  if (ph < 4) src = w1 + (size_t)(e * 256 + r) * 256 + ph * 64 + kc * 8;
  else        src = w2 + (size_t)e * 65536 + (size_t)r * 256 + (ph - 4) * 64 + kc * 8;
  float4 v0 = *reinterpret_cast<const float4*>(src);
  float4 v1 = *reinterpret_cast<const float4*>(src + 4);
  uint4 pk;
  pk.x = pack_bf2(v0.x, v0.y);
  pk.y = pack_bf2(v0.z, v0.w);
  pk.z = pack_bf2(v1.x, v1.y);
  pk.w = pack_bf2(v1.z, v1.w);
  *reinterpret_cast<uint4*>(g_wimg + (size_t)s * STAGE_BYTES + r * 128 +
                            ((kc ^ (r & 7)) << 4)) = pk;
}

// ---------------------------------------------------------------------------
// Main fused kernel.
// ---------------------------------------------------------------------------
__global__ __launch_bounds__(NTHR, 2)
void moe_mma_kernel(const float* __restrict__ x,
                    const float* __restrict__ gate_w,
                    const float* __restrict__ gate_b,
                    const float* __restrict__ b1,
                    const float* __restrict__ b2,
                    float* __restrict__ out) {
  extern __shared__ __align__(16) unsigned char smraw[];
  const uint32_t smb = smem_u32(smraw);
  float* gws  = reinterpret_cast<float*>(smraw + SM_GW);
  float* b1s  = reinterpret_cast<float*>(smraw + SM_B1);
  float* b2s  = reinterpret_cast<float*>(smraw + SM_B2);
  float* sp   = reinterpret_cast<float*>(smraw + SM_SP);
  float* wts  = reinterpret_cast<float*>(smraw + SM_WT);

  const int tid  = threadIdx.x;
  const int lane = tid & 31;
  const int wn   = tid >> 5;   // 0..7: out-col block (32 cols)

  const int token0 = blockIdx.x * TM;
  const int bidx   = token0 / THW;
  const int s0     = token0 % THW;
  const float* xb = x   + (size_t)bidx * C * THW + s0;
  float*       ob = out + (size_t)bidx * C * THW + s0;

  // --- kick stage 0 weight copy immediately -------------------------------
  {
    const unsigned char* src = g_wimg;
#pragma unroll
    for (int it = 0; it < 8; ++it) {
      int off = it * 4096 + tid * 16;
      cp16(smb + SM_WBUF0 + off, src + off);
    }
    cp_commit();
  }

  // --- stage gate_w / b1 / b2 ---------------------------------------------
#pragma unroll
  for (int rr = 0; rr < 4; ++rr) {
    int i = rr * NTHR + tid;
    gws[i] = gate_w[i];
    b1s[i] = b1[i];
    b2s[i] = b2[i];
  }
  __syncthreads();

  // --- x staging (fp32->bf16, swizzled) + fp32 gate logit partials --------
  {
    const int t   = tid & 31;
    const int cpg = tid >> 5;  // 0..7
    float l[4] = {0.f, 0.f, 0.f, 0.f};
    const float* gx = xb + t;
#pragma unroll
    for (int it = 0; it < 16; ++it) {
      int c0 = it * 16 + cpg * 2;
      float v0 = __ldg(gx + (size_t)c0 * THW);
      float v1 = __ldg(gx + (size_t)(c0 + 1) * THW);
#pragma unroll
      for (int e = 0; e < 4; ++e)
        l[e] = fmaf(gws[e * 256 + c0], v0, fmaf(gws[e * 256 + c0 + 1], v1, l[e]));
      uint32_t pk = pack_bf2(v0, v1);
      uint32_t off = t * 512 + (((c0 >> 3) ^ (t & 7)) << 4) + (c0 & 7) * 2;
      *reinterpret_cast<uint32_t*>(smraw + SM_XS + off) = pk;
    }
#pragma unroll
    for (int e = 0; e < 4; ++e) sp[cpg * 128 + t * 4 + e] = l[e];
  }
  __syncthreads();

  // --- logits reduce + top-2 softmax --------------------------------------
  if (tid < 32) {
    float l[4];
#pragma unroll
    for (int e = 0; e < 4; ++e) {
      float s = __ldg(gate_b + e);
#pragma unroll
      for (int g = 0; g < 8; ++g) s += sp[g * 128 + tid * 4 + e];
      l[e] = s;
    }
    float v1 = l[0]; int i1 = 0;
    if (l[1] > v1) { v1 = l[1]; i1 = 1; }
    if (l[2] > v1) { v1 = l[2]; i1 = 2; }
    if (l[3] > v1) { v1 = l[3]; i1 = 3; }
    float v2 = -3.402823e38f; int i2 = 0;
#pragma unroll
    for (int e = 0; e < 4; ++e)
      if (e != i1 && l[e] > v2) { v2 = l[e]; i2 = e; }
    float e2  = __expf(v2 - v1);
    float inv = 1.0f / (1.0f + e2);
    wts[tid * 4 + 0] = 0.f; wts[tid * 4 + 1] = 0.f;
    wts[tid * 4 + 2] = 0.f; wts[tid * 4 + 3] = 0.f;
    wts[tid * 4 + i1] = inv;
    wts[tid * 4 + i2] = e2 * inv;
  }
  __syncthreads();

  // --- precompute ldsm addresses (loop-invariant) -------------------------
  // A: addr = (SM_XS|SM_HS base) + row*512 + ((kc^r)<<4); kc = ph*8 + q,
  //    q = (kq*2+ks)*2 + (mi>>1).  ph*8 has no low-3 bits -> kc^r = ph*8+(q^r)
  //    => addr = aofs[] + hs_sel*16384 + ph*128.
  // B: addr = wbuf + (wn*32+nt*8+r)*128 + (((kq*4+mi)^r)<<4) = wbuf + bofs[].
  uint32_t aofs[8], bofs[8];
  {
    const int r  = lane & 7;
    const int mi = lane >> 3;
#pragma unroll
    for (int mt = 0; mt < 2; ++mt)
#pragma unroll
      for (int kq = 0; kq < 2; ++kq)
#pragma unroll
        for (int ks = 0; ks < 2; ++ks) {
          int row = mt * 16 + (mi & 1) * 8 + r;
          int q   = (kq * 2 + ks) * 2 + (mi >> 1);
          aofs[mt * 4 + kq * 2 + ks] =
              smb + SM_XS + (uint32_t)row * 512 + (uint32_t)((q ^ r) << 4);
        }
#pragma unroll
    for (int nt = 0; nt < 4; ++nt)
#pragma unroll
      for (int kq = 0; kq < 2; ++kq) {
        int kc = kq * 4 + mi;
        bofs[nt * 2 + kq] = (uint32_t)(wn * 32 + nt * 8 + r) * 128 +
                            (uint32_t)((kc ^ r) << 4);
      }
  }

  // --- main pipelined loop over 32 weight stages --------------------------
  float acc1[2][4][4], acc2[2][4][4];
#pragma unroll
  for (int mt = 0; mt < 2; ++mt)
#pragma unroll
    for (int nt = 0; nt < 4; ++nt)
#pragma unroll
      for (int j = 0; j < 4; ++j) acc2[mt][nt][j] = 0.f;

  const unsigned char* gsrc = g_wimg + STAGE_BYTES;  // stage 1 source
#pragma unroll 1
  for (int s = 0; s < NSTAGE; ++s) {
    if (s + 1 < NSTAGE) {  // prefetch next stage into the other buffer
      uint32_t dst = smb + (((s + 1) & 1) ? SM_WBUF1 : SM_WBUF0) + tid * 16;
      const unsigned char* sp8 = gsrc + tid * 16;
#pragma unroll
      for (int it = 0; it < 8; ++it)
        cp16(dst + it * 4096, sp8 + it * 4096);
      cp_commit();
      gsrc += STAGE_BYTES;
      cp_wait<1>();
    } else {
      cp_wait<0>();
    }
    __syncthreads();

    const int ph = s & 7, e = s >> 3;
    const uint32_t wbuf = smb + ((s & 1) ? SM_WBUF1 : SM_WBUF0);

    if (ph < 4) {
      if (ph == 0) {
#pragma unroll
        for (int mt = 0; mt < 2; ++mt)
#pragma unroll
          for (int nt = 0; nt < 4; ++nt)
#pragma unroll
            for (int j = 0; j < 4; ++j) acc1[mt][nt][j] = 0.f;
      }
      run_stage(acc1, aofs, (uint32_t)(ph * 128), bofs, wbuf);
      if (ph == 3) {
        // h epilogue: +b1, SiLU, x gate weight, pack bf16 -> hs
#pragma unroll
        for (int mt = 0; mt < 2; ++mt) {
          const int tok1 = mt * 16 + (lane >> 2);
          const int tok2 = tok1 + 8;
          const float wt1 = wts[tok1 * 4 + e];
          const float wt2 = wts[tok2 * 4 + e];
#pragma unroll
          for (int nt = 0; nt < 4; ++nt) {
            int n = wn * 32 + nt * 8 + (lane & 3) * 2;
            float ba = b1s[e * 256 + n], bb = b1s[e * 256 + n + 1];
            float h0 = acc1[mt][nt][0] + ba, h1 = acc1[mt][nt][1] + bb;
            float h2 = acc1[mt][nt][2] + ba, h3 = acc1[mt][nt][3] + bb;
            h0 = h0 * (1.0f / (1.0f + __expf(-h0))) * wt1;
            h1 = h1 * (1.0f / (1.0f + __expf(-h1))) * wt1;
            h2 = h2 * (1.0f / (1.0f + __expf(-h2))) * wt2;
            h3 = h3 * (1.0f / (1.0f + __expf(-h3))) * wt2;
            uint32_t o1 = tok1 * 512 + (((n >> 3) ^ (tok1 & 7)) << 4) + (n & 7) * 2;
            uint32_t o2 = tok2 * 512 + (((n >> 3) ^ (tok2 & 7)) << 4) + (n & 7) * 2;
            *reinterpret_cast<uint32_t*>(smraw + SM_HS + o1) = pack_bf2(h0, h1);
            *reinterpret_cast<uint32_t*>(smraw + SM_HS + o2) = pack_bf2(h2, h3);
          }
        }
      }
    } else {
      run_stage(acc2, aofs, (uint32_t)(16384 + (ph - 4) * 128), bofs, wbuf);
    }
    __syncthreads();
  }

  // --- final epilogue: acc2 -> smem (coalescing relay) -> global ----------
  float* d2s = reinterpret_cast<float*>(smraw);  // overlays weight buffers
  {
    const int tok1 = lane >> 2;
    const int tok2 = tok1 + 8;
#pragma unroll
    for (int mt = 0; mt < 2; ++mt) {
      const int t1 = mt * 16 + tok1;
      const int t2 = mt * 16 + tok2;
#pragma unroll
      for (int nt = 0; nt < 4; ++nt) {
        int n = wn * 32 + nt * 8 + (lane & 3) * 2;
        *reinterpret_cast<float2*>(d2s + t1 * 258 + n) =
            make_float2(acc2[mt][nt][0], acc2[mt][nt][1]);
        *reinterpret_cast<float2*>(d2s + t2 * 258 + n) =
            make_float2(acc2[mt][nt][2], acc2[mt][nt][3]);
      }
    }
  }
  __syncthreads();
  {
    const int t  = tid & 31;
    const int cg = tid >> 5;   // 0..7
    const float w0 = wts[t * 4 + 0], w1w = wts[t * 4 + 1];
    const float w2w = wts[t * 4 + 2], w3 = wts[t * 4 + 3];
#pragma unroll 4
    for (int i = 0; i < 32; ++i) {
      int ch = i * 8 + cg;
      float v = d2s[t * 258 + ch]
              + w0  * b2s[ch]       + w1w * b2s[256 + ch]
              + w2w * b2s[512 + ch] + w3  * b2s[768 + ch]
              + __ldg(xb + (size_t)ch * THW + t);
      ob[(size_t)ch * THW + t] = v;
    }
  }
}

// ---------------------------------------------------------------------------
extern "C" void kernel_launch(void* const* d_in, const int* in_sizes, int n_in,
                              void* d_out, int out_size) {
  const float* x      = (const float*)d_in[0];
  const float* gate_w = (const float*)d_in[1];
  const float* gate_b = (const float*)d_in[2];
  const float* w1     = (const float*)d_in[3];
  const float* b1     = (const float*)d_in[4];
  const float* w2     = (const float*)d_in[5];
  const float* b2     = (const float*)d_in[6];
  float* out          = (float*)d_out;
  (void)in_sizes; (void)n_in; (void)out_size;

  prep_weights<<<256, 256>>>(w1, w2);

  cudaFuncSetAttribute(moe_mma_kernel,
                       cudaFuncAttributeMaxDynamicSharedMemorySize, SM_TOTAL);
  moe_mma_kernel<<<NCTA, NTHR, SM_TOTAL>>>(x, gate_w, gate_b, b1, b2, out);
}

// round 14
// speedup vs baseline: 1.3343x; 1.1479x over previous
#include <cuda_runtime.h>
#include <cuda_bf16.h>
#include <cstdint>
#include <math.h>

// ===========================================================================
// Fused MoE: gate(top-2 softmax, fp32) + layer1(+SiLU) + grouped layer2 +
// weighted combine + residual.  bf16 mma.sync.m16n8k16.
// R14: warp-autonomous weight pipeline. Each warp cp.asyncs ITS OWN 4KB
// slice of each stage and syncs with wait_group+syncwarp only; CTA barriers
// just at the HS handoff (2 per expert, was 2 per stage = 64).
// ===========================================================================

namespace {
constexpr int C    = 256;
constexpr int E    = 4;
constexpr int THW  = 16 * 32 * 32;   // 16384
constexpr int NTOK = 2 * THW;        // 32768
constexpr int TM   = 32;             // tokens per CTA
constexpr int NCTA = NTOK / TM;      // 1024
constexpr int NTHR = 256;            // 8 warps

constexpr int NSTAGE      = 32;      // e*8 + phase (0-3: w1 kq, 4-7: w2 kq)
constexpr int STAGE_BYTES = 32768;   // 256 rows x 64 k x bf16 (swizzled)

// shared memory byte offsets
constexpr int SM_WBUF0 = 0;
constexpr int SM_WBUF1 = 32768;
constexpr int SM_XS    = 65536;            // x bf16 [32][256] swizzled (16 KB)
constexpr int SM_HS    = 81920;            // h bf16 [32][256] swizzled (16 KB)
constexpr int SM_B1    = 98304;            // b1 fp32 [1024]
constexpr int SM_B2    = 102400;           // b2 fp32 [1024]
constexpr int SM_WT    = 106496;           // gate weights [32][4] fp32
constexpr int SM_TOTAL = 107008;           // 104.5 KB -> 2 CTAs/SM
// gating-phase overlays (HS unused then)
constexpr int SM_GW    = SM_HS;            // gate_w fp32 [1024]
constexpr int SM_SP    = SM_HS + 4096;     // logit partials [8][32][4]
}  // namespace

__device__ __align__(16) unsigned char g_wimg[NSTAGE * STAGE_BYTES];

// ------------------------------ helpers -----------------------------------
__device__ __forceinline__ uint32_t smem_u32(const void* p) {
  uint32_t a;
  asm("{ .reg .u64 t; cvta.to.shared.u64 t, %1; cvt.u32.u64 %0, t; }"
      : "=r"(a) : "l"(p));
  return a;
}
__device__ __forceinline__ void ldsm4(uint32_t* r, uint32_t addr) {
  asm volatile("ldmatrix.sync.aligned.m8n8.x4.shared.b16 {%0,%1,%2,%3}, [%4];"
               : "=r"(r[0]), "=r"(r[1]), "=r"(r[2]), "=r"(r[3]) : "r"(addr));
}
__device__ __forceinline__ void mma16816(float* d, const uint32_t* a,
                                         const uint32_t* b) {
  asm volatile(
      "mma.sync.aligned.m16n8k16.row.col.f32.bf16.bf16.f32 "
      "{%0,%1,%2,%3}, {%4,%5,%6,%7}, {%8,%9}, {%0,%1,%2,%3};"
      : "+f"(d[0]), "+f"(d[1]), "+f"(d[2]), "+f"(d[3])
      : "r"(a[0]), "r"(a[1]), "r"(a[2]), "r"(a[3]), "r"(b[0]), "r"(b[1]));
}
__device__ __forceinline__ void cp16(uint32_t dst, const void* src) {
  asm volatile("cp.async.cg.shared.global [%0], [%1], 16;"
               :: "r"(dst), "l"(src));
}
__device__ __forceinline__ void cp_commit() {
  asm volatile("cp.async.commit_group;" ::: "memory");
}
template <int N>
__device__ __forceinline__ void cp_wait() {
  asm volatile("cp.async.wait_group %0;" :: "n"(N) : "memory");
}
__device__ __forceinline__ uint32_t pack_bf2(float a, float b) {
  __nv_bfloat162 t = __floats2bfloat162_rn(a, b);  // .x = a (low)
  return *reinterpret_cast<uint32_t*>(&t);
}

// One 64-k stage, warp tile M=32 N=32 K=64, precomputed addresses.
__device__ __forceinline__ void run_stage(float (&acc)[2][4][4],
                                          const uint32_t (&aofs)[8],
                                          uint32_t asel,
                                          const uint32_t (&bofs)[8],
                                          uint32_t wbuf) {
#pragma unroll
  for (int kq = 0; kq < 2; ++kq) {
    uint32_t a[2][2][4];
#pragma unroll
    for (int mt = 0; mt < 2; ++mt)
#pragma unroll
      for (int ks = 0; ks < 2; ++ks)
        ldsm4(a[mt][ks], aofs[mt * 4 + kq * 2 + ks] + asel);
#pragma unroll
    for (int nt = 0; nt < 4; ++nt) {
      uint32_t b[4];
      ldsm4(b, wbuf + bofs[nt * 2 + kq]);
#pragma unroll
      for (int mt = 0; mt < 2; ++mt) {
        mma16816(acc[mt][nt], a[mt][0], b);
        mma16816(acc[mt][nt], a[mt][1], b + 2);
      }
    }
  }
}

// ---------------------------------------------------------------------------
// Prologue: bf16 swizzled weight images (32 stages x 256 rows x 64 k).
// ---------------------------------------------------------------------------
__global__ void prep_weights(const float* __restrict__ w1,
                             const float* __restrict__ w2) {
  int idx = blockIdx.x * blockDim.x + threadIdx.x;  // 65536 threads
  int s  = idx >> 11;          // stage (2048 uint4 per stage)
  int r  = (idx >> 3) & 255;   // row (out/hidden channel)
  int kc = idx & 7;            // 16B chunk within 64-k row
  int e = s >> 3, ph = s & 7;
  const float* src;
  if (ph < 4) src = w1 + (size_t)(e * 256 + r) * 256 + ph * 64 + kc * 8;
  else        src = w2 + (size_t)e * 65536 + (size_t)r * 256 + (ph - 4) * 64 + kc * 8;
  float4 v0 = *reinterpret_cast<const float4*>(src);
  float4 v1 = *reinterpret_cast<const float4*>(src + 4);
  uint4 pk;
  pk.x = pack_bf2(v0.x, v0.y);
  pk.y = pack_bf2(v0.z, v0.w);
  pk.z = pack_bf2(v1.x, v1.y);
  pk.w = pack_bf2(v1.z, v1.w);
  *reinterpret_cast<uint4*>(g_wimg + (size_t)s * STAGE_BYTES + r * 128 +
                            ((kc ^ (r & 7)) << 4)) = pk;
}

// ---------------------------------------------------------------------------
// Main fused kernel.
// ---------------------------------------------------------------------------
__global__ __launch_bounds__(NTHR, 2)
void moe_mma_kernel(const float* __restrict__ x,
                    const float* __restrict__ gate_w,
                    const float* __restrict__ gate_b,
                    const float* __restrict__ b1,
                    const float* __restrict__ b2,
                    float* __restrict__ out) {
  extern __shared__ __align__(16) unsigned char smraw[];
  const uint32_t smb = smem_u32(smraw);
  float* gws  = reinterpret_cast<float*>(smraw + SM_GW);
  float* b1s  = reinterpret_cast<float*>(smraw + SM_B1);
  float* b2s  = reinterpret_cast<float*>(smraw + SM_B2);
  float* sp   = reinterpret_cast<float*>(smraw + SM_SP);
  float* wts  = reinterpret_cast<float*>(smraw + SM_WT);

  const int tid  = threadIdx.x;
  const int lane = tid & 31;
  const int wn   = tid >> 5;   // 0..7: out-col block (32 cols)

  const int token0 = blockIdx.x * TM;
  const int bidx   = token0 / THW;
  const int s0     = token0 % THW;
  const float* xb = x   + (size_t)bidx * C * THW + s0;
  float*       ob = out + (size_t)bidx * C * THW + s0;

  // warp-slice copy geometry: warp wn owns bytes [wn*4096, wn*4096+4096)
  const uint32_t slice_off = (uint32_t)(wn * 4096 + lane * 16);

  // --- kick stage 0 weight copy (own slice) -------------------------------
  {
    const unsigned char* src = g_wimg + slice_off;
    uint32_t dst = smb + SM_WBUF0 + slice_off;
#pragma unroll
    for (int it = 0; it < 8; ++it)
      cp16(dst + it * 512, src + it * 512);
    cp_commit();
  }

  // --- stage gate_w / b1 / b2 ---------------------------------------------
#pragma unroll
  for (int rr = 0; rr < 4; ++rr) {
    int i = rr * NTHR + tid;
    gws[i] = gate_w[i];
    b1s[i] = b1[i];
    b2s[i] = b2[i];
  }
  __syncthreads();

  // --- x staging (fp32->bf16, swizzled) + fp32 gate logit partials --------
  {
    const int t   = tid & 31;
    const int cpg = tid >> 5;  // 0..7
    float l[4] = {0.f, 0.f, 0.f, 0.f};
    const float* gx = xb + t;
#pragma unroll
    for (int it = 0; it < 16; ++it) {
      int c0 = it * 16 + cpg * 2;
      float v0 = __ldg(gx + (size_t)c0 * THW);
      float v1 = __ldg(gx + (size_t)(c0 + 1) * THW);
#pragma unroll
      for (int e = 0; e < 4; ++e)
        l[e] = fmaf(gws[e * 256 + c0], v0, fmaf(gws[e * 256 + c0 + 1], v1, l[e]));
      uint32_t pk = pack_bf2(v0, v1);
      uint32_t off = t * 512 + (((c0 >> 3) ^ (t & 7)) << 4) + (c0 & 7) * 2;
      *reinterpret_cast<uint32_t*>(smraw + SM_XS + off) = pk;
    }
#pragma unroll
    for (int e = 0; e < 4; ++e) sp[cpg * 128 + t * 4 + e] = l[e];
  }
  __syncthreads();

  // --- logits reduce + top-2 softmax --------------------------------------
  if (tid < 32) {
    float l[4];
#pragma unroll
    for (int e = 0; e < 4; ++e) {
      float s = __ldg(gate_b + e);
#pragma unroll
      for (int g = 0; g < 8; ++g) s += sp[g * 128 + tid * 4 + e];
      l[e] = s;
    }
    float v1 = l[0]; int i1 = 0;
    if (l[1] > v1) { v1 = l[1]; i1 = 1; }
    if (l[2] > v1) { v1 = l[2]; i1 = 2; }
    if (l[3] > v1) { v1 = l[3]; i1 = 3; }
    float v2 = -3.402823e38f; int i2 = 0;
#pragma unroll
    for (int e = 0; e < 4; ++e)
      if (e != i1 && l[e] > v2) { v2 = l[e]; i2 = e; }
    float e2  = __expf(v2 - v1);
    float inv = 1.0f / (1.0f + e2);
    wts[tid * 4 + 0] = 0.f; wts[tid * 4 + 1] = 0.f;
    wts[tid * 4 + 2] = 0.f; wts[tid * 4 + 3] = 0.f;
    wts[tid * 4 + i1] = inv;
    wts[tid * 4 + i2] = e2 * inv;
  }
  __syncthreads();  // wts visible; gating overlays (gws/sp in HS) dead

  // --- precompute ldsm addresses (loop-invariant) -------------------------
  uint32_t aofs[8], bofs[8];
  {
    const int r  = lane & 7;
    const int mi = lane >> 3;
#pragma unroll
    for (int mt = 0; mt < 2; ++mt)
#pragma unroll
      for (int kq = 0; kq < 2; ++kq)
#pragma unroll
        for (int ks = 0; ks < 2; ++ks) {
          int row = mt * 16 + (mi & 1) * 8 + r;
          int q   = (kq * 2 + ks) * 2 + (mi >> 1);
          aofs[mt * 4 + kq * 2 + ks] =
              smb + SM_XS + (uint32_t)row * 512 + (uint32_t)((q ^ r) << 4);
        }
#pragma unroll
    for (int nt = 0; nt < 4; ++nt)
#pragma unroll
      for (int kq = 0; kq < 2; ++kq) {
        int kc = kq * 4 + mi;
        bofs[nt * 2 + kq] = (uint32_t)(wn * 32 + nt * 8 + r) * 128 +
                            (uint32_t)((kc ^ r) << 4);
      }
  }

  // --- main loop: warp-autonomous over 32 weight stages -------------------
  // Per stage: wait OWN slice (wait_group+syncwarp), prefetch own slice of
  // next stage, compute.  CTA barriers only at HS handoffs (ph3 write / ph4
  // read).  No cross-warp hazard on weight buffers: each warp writes & reads
  // only its own 4KB slice.
  float acc1[2][4][4], acc2[2][4][4];
#pragma unroll
  for (int mt = 0; mt < 2; ++mt)
#pragma unroll
    for (int nt = 0; nt < 4; ++nt)
#pragma unroll
      for (int j = 0; j < 4; ++j) acc2[mt][nt][j] = 0.f;

  const unsigned char* gsrc = g_wimg + STAGE_BYTES + slice_off;  // stage 1
#pragma unroll 1
  for (int s = 0; s < NSTAGE; ++s) {
    if (s + 1 < NSTAGE) {  // prefetch own slice of next stage
      uint32_t dst = smb + (((s + 1) & 1) ? SM_WBUF1 : SM_WBUF0) + slice_off;
#pragma unroll
      for (int it = 0; it < 8; ++it)
        cp16(dst + it * 512, gsrc + it * 512);
      cp_commit();
      gsrc += STAGE_BYTES;
      cp_wait<1>();
    } else {
      cp_wait<0>();
    }
    __syncwarp();

    const int ph = s & 7, e = s >> 3;
    const uint32_t wbuf = smb + ((s & 1) ? SM_WBUF1 : SM_WBUF0);

    if (ph < 4) {
      if (ph == 0) {
#pragma unroll
        for (int mt = 0; mt < 2; ++mt)
#pragma unroll
          for (int nt = 0; nt < 4; ++nt)
#pragma unroll
            for (int j = 0; j < 4; ++j) acc1[mt][nt][j] = 0.f;
      }
      run_stage(acc1, aofs, (uint32_t)(ph * 128), bofs, wbuf);
      if (ph == 3) {
        __syncthreads();  // prev expert's HS readers (ph4-7) all done
        // h epilogue: +b1, SiLU, x gate weight, pack bf16 -> hs
#pragma unroll
        for (int mt = 0; mt < 2; ++mt) {
          const int tok1 = mt * 16 + (lane >> 2);
          const int tok2 = tok1 + 8;
          const float wt1 = wts[tok1 * 4 + e];
          const float wt2 = wts[tok2 * 4 + e];
#pragma unroll
          for (int nt = 0; nt < 4; ++nt) {
            int n = wn * 32 + nt * 8 + (lane & 3) * 2;
            float ba = b1s[e * 256 + n], bb = b1s[e * 256 + n + 1];
            float h0 = acc1[mt][nt][0] + ba, h1 = acc1[mt][nt][1] + bb;
            float h2 = acc1[mt][nt][2] + ba, h3 = acc1[mt][nt][3] + bb;
            h0 = h0 * (1.0f / (1.0f + __expf(-h0))) * wt1;
            h1 = h1 * (1.0f / (1.0f + __expf(-h1))) * wt1;
            h2 = h2 * (1.0f / (1.0f + __expf(-h2))) * wt2;
            h3 = h3 * (1.0f / (1.0f + __expf(-h3))) * wt2;
            uint32_t o1 = tok1 * 512 + (((n >> 3) ^ (tok1 & 7)) << 4) + (n & 7) * 2;
            uint32_t o2 = tok2 * 512 + (((n >> 3) ^ (tok2 & 7)) << 4) + (n & 7) * 2;
            *reinterpret_cast<uint32_t*>(smraw + SM_HS + o1) = pack_bf2(h0, h1);
            *reinterpret_cast<uint32_t*>(smraw + SM_HS + o2) = pack_bf2(h2, h3);
          }
        }
      }
    } else {
      if (ph == 4) __syncthreads();  // all HS writes visible
      run_stage(acc2, aofs, (uint32_t)(16384 + (ph - 4) * 128), bofs, wbuf);
    }
  }
  __syncthreads();  // all warps done before d2s overlays weight buffers

  // --- final epilogue: acc2 -> smem (coalescing relay) -> global ----------
  float* d2s = reinterpret_cast<float*>(smraw);  // overlays weight buffers
  {
    const int tok1 = lane >> 2;
    const int tok2 = tok1 + 8;
#pragma unroll
    for (int mt = 0; mt < 2; ++mt) {
      const int t1 = mt * 16 + tok1;
      const int t2 = mt * 16 + tok2;
#pragma unroll
      for (int nt = 0; nt < 4; ++nt) {
        int n = wn * 32 + nt * 8 + (lane & 3) * 2;
        *reinterpret_cast<float2*>(d2s + t1 * 258 + n) =
            make_float2(acc2[mt][nt][0], acc2[mt][nt][1]);
        *reinterpret_cast<float2*>(d2s + t2 * 258 + n) =
            make_float2(acc2[mt][nt][2], acc2[mt][nt][3]);
      }
    }
  }
  __syncthreads();
  {
    const int t  = tid & 31;
    const int cg = tid >> 5;   // 0..7
    const float w0 = wts[t * 4 + 0], w1w = wts[t * 4 + 1];
    const float w2w = wts[t * 4 + 2], w3 = wts[t * 4 + 3];
#pragma unroll 4
    for (int i = 0; i < 32; ++i) {
      int ch = i * 8 + cg;
      float v = d2s[t * 258 + ch]
              + w0  * b2s[ch]       + w1w * b2s[256 + ch]
              + w2w * b2s[512 + ch] + w3  * b2s[768 + ch]
              + __ldg(xb + (size_t)ch * THW + t);
      ob[(size_t)ch * THW + t] = v;
    }
  }
}

// ---------------------------------------------------------------------------
extern "C" void kernel_launch(void* const* d_in, const int* in_sizes, int n_in,
                              void* d_out, int out_size) {
  const float* x      = (const float*)d_in[0];
  const float* gate_w = (const float*)d_in[1];
  const float* gate_b = (const float*)d_in[2];
  const float* w1     = (const float*)d_in[3];
  const float* b1     = (const float*)d_in[4];
  const float* w2     = (const float*)d_in[5];
  const float* b2     = (const float*)d_in[6];
  float* out          = (float*)d_out;
  (void)in_sizes; (void)n_in; (void)out_size;

  prep_weights<<<256, 256>>>(w1, w2);

  cudaFuncSetAttribute(moe_mma_kernel,
                       cudaFuncAttributeMaxDynamicSharedMemorySize, SM_TOTAL);
  moe_mma_kernel<<<NCTA, NTHR, SM_TOTAL>>>(x, gate_w, gate_b, b1, b2, out);
}

// round 15
// speedup vs baseline: 1.3768x; 1.0319x over previous
#include <cuda_runtime.h>
#include <cuda_bf16.h>
#include <cstdint>
#include <math.h>

// ===========================================================================
// Fused MoE: gate(top-2 softmax, fp32) + layer1(+SiLU) + grouped layer2 +
// weighted combine + residual.  bf16 mma.sync.m16n8k16.
// R15: R14 (warp-autonomous weight pipeline) + batched ldsm per kq (8 ldsm
// issued back-to-back before 16 MMAs -> 2 instead of 8 exposed LDS latencies
// per stage) + 8x-unrolled stage loop (compile-time ph: buffer parity, asel,
// branches all fold).
// ===========================================================================

namespace {
constexpr int C    = 256;
constexpr int E    = 4;
constexpr int THW  = 16 * 32 * 32;   // 16384
constexpr int NTOK = 2 * THW;        // 32768
constexpr int TM   = 32;             // tokens per CTA
constexpr int NCTA = NTOK / TM;      // 1024
constexpr int NTHR = 256;            // 8 warps

constexpr int NSTAGE      = 32;      // e*8 + phase (0-3: w1 kq, 4-7: w2 kq)
constexpr int STAGE_BYTES = 32768;   // 256 rows x 64 k x bf16 (swizzled)

// shared memory byte offsets
constexpr int SM_WBUF0 = 0;
constexpr int SM_WBUF1 = 32768;
constexpr int SM_XS    = 65536;            // x bf16 [32][256] swizzled (16 KB)
constexpr int SM_HS    = 81920;            // h bf16 [32][256] swizzled (16 KB)
constexpr int SM_B1    = 98304;            // b1 fp32 [1024]
constexpr int SM_B2    = 102400;           // b2 fp32 [1024]
constexpr int SM_WT    = 106496;           // gate weights [32][4] fp32
constexpr int SM_TOTAL = 107008;           // 104.5 KB -> 2 CTAs/SM
// gating-phase overlays (HS unused then)
constexpr int SM_GW    = SM_HS;            // gate_w fp32 [1024]
constexpr int SM_SP    = SM_HS + 4096;     // logit partials [8][32][4]
}  // namespace

__device__ __align__(16) unsigned char g_wimg[NSTAGE * STAGE_BYTES];

// ------------------------------ helpers -----------------------------------
__device__ __forceinline__ uint32_t smem_u32(const void* p) {
  uint32_t a;
  asm("{ .reg .u64 t; cvta.to.shared.u64 t, %1; cvt.u32.u64 %0, t; }"
      : "=r"(a) : "l"(p));
  return a;
}
__device__ __forceinline__ void ldsm4(uint32_t* r, uint32_t addr) {
  asm volatile("ldmatrix.sync.aligned.m8n8.x4.shared.b16 {%0,%1,%2,%3}, [%4];"
               : "=r"(r[0]), "=r"(r[1]), "=r"(r[2]), "=r"(r[3]) : "r"(addr));
}
__device__ __forceinline__ void mma16816(float* d, const uint32_t* a,
                                         const uint32_t* b) {
  asm volatile(
      "mma.sync.aligned.m16n8k16.row.col.f32.bf16.bf16.f32 "
      "{%0,%1,%2,%3}, {%4,%5,%6,%7}, {%8,%9}, {%0,%1,%2,%3};"
      : "+f"(d[0]), "+f"(d[1]), "+f"(d[2]), "+f"(d[3])
      : "r"(a[0]), "r"(a[1]), "r"(a[2]), "r"(a[3]), "r"(b[0]), "r"(b[1]));
}
__device__ __forceinline__ void cp16(uint32_t dst, const void* src) {
  asm volatile("cp.async.cg.shared.global [%0], [%1], 16;"
               :: "r"(dst), "l"(src));
}
__device__ __forceinline__ void cp_commit() {
  asm volatile("cp.async.commit_group;" ::: "memory");
}
template <int N>
__device__ __forceinline__ void cp_wait() {
  asm volatile("cp.async.wait_group %0;" :: "n"(N) : "memory");
}
__device__ __forceinline__ uint32_t pack_bf2(float a, float b) {
  __nv_bfloat162 t = __floats2bfloat162_rn(a, b);  // .x = a (low)
  return *reinterpret_cast<uint32_t*>(&t);
}

// One 64-k stage, warp tile M=32 N=32 K=64, precomputed addresses.
// Batched issue: per kq, all 8 ldsm first (A then B), then 16 MMAs.
__device__ __forceinline__ void run_stage(float (&acc)[2][4][4],
                                          const uint32_t (&aofs)[8],
                                          uint32_t asel,
                                          const uint32_t (&bofs)[8],
                                          uint32_t wbuf) {
#pragma unroll
  for (int kq = 0; kq < 2; ++kq) {
    uint32_t a[2][2][4];
    uint32_t b[4][4];
#pragma unroll
    for (int mt = 0; mt < 2; ++mt)
#pragma unroll
      for (int ks = 0; ks < 2; ++ks)
        ldsm4(a[mt][ks], aofs[mt * 4 + kq * 2 + ks] + asel);
#pragma unroll
    for (int nt = 0; nt < 4; ++nt)
      ldsm4(b[nt], wbuf + bofs[nt * 2 + kq]);
#pragma unroll
    for (int nt = 0; nt < 4; ++nt)
#pragma unroll
      for (int mt = 0; mt < 2; ++mt) {
        mma16816(acc[mt][nt], a[mt][0], b[nt]);
        mma16816(acc[mt][nt], a[mt][1], b[nt] + 2);
      }
  }
}

// ---------------------------------------------------------------------------
// Prologue: bf16 swizzled weight images (32 stages x 256 rows x 64 k).
// ---------------------------------------------------------------------------
__global__ void prep_weights(const float* __restrict__ w1,
                             const float* __restrict__ w2) {
  int idx = blockIdx.x * blockDim.x + threadIdx.x;  // 65536 threads
  int s  = idx >> 11;          // stage (2048 uint4 per stage)
  int r  = (idx >> 3) & 255;   // row (out/hidden channel)
  int kc = idx & 7;            // 16B chunk within 64-k row
  int e = s >> 3, ph = s & 7;
  const float* src;
  if (ph < 4) src = w1 + (size_t)(e * 256 + r) * 256 + ph * 64 + kc * 8;
  else        src = w2 + (size_t)e * 65536 + (size_t)r * 256 + (ph - 4) * 64 + kc * 8;
  float4 v0 = *reinterpret_cast<const float4*>(src);
  float4 v1 = *reinterpret_cast<const float4*>(src + 4);
  uint4 pk;
  pk.x = pack_bf2(v0.x, v0.y);
  pk.y = pack_bf2(v0.z, v0.w);
  pk.z = pack_bf2(v1.x, v1.y);
  pk.w = pack_bf2(v1.z, v1.w);
  *reinterpret_cast<uint4*>(g_wimg + (size_t)s * STAGE_BYTES + r * 128 +
                            ((kc ^ (r & 7)) << 4)) = pk;
}

// ---------------------------------------------------------------------------
// Main fused kernel.
// ---------------------------------------------------------------------------
__global__ __launch_bounds__(NTHR, 2)
void moe_mma_kernel(const float* __restrict__ x,
                    const float* __restrict__ gate_w,
                    const float* __restrict__ gate_b,
                    const float* __restrict__ b1,
                    const float* __restrict__ b2,
                    float* __restrict__ out) {
  extern __shared__ __align__(16) unsigned char smraw[];
  const uint32_t smb = smem_u32(smraw);
  float* gws  = reinterpret_cast<float*>(smraw + SM_GW);
  float* b1s  = reinterpret_cast<float*>(smraw + SM_B1);
  float* b2s  = reinterpret_cast<float*>(smraw + SM_B2);
  float* sp   = reinterpret_cast<float*>(smraw + SM_SP);
  float* wts  = reinterpret_cast<float*>(smraw + SM_WT);

  const int tid  = threadIdx.x;
  const int lane = tid & 31;
  const int wn   = tid >> 5;   // 0..7: out-col block (32 cols)

  const int token0 = blockIdx.x * TM;
  const int bidx   = token0 / THW;
  const int s0     = token0 % THW;
  const float* xb = x   + (size_t)bidx * C * THW + s0;
  float*       ob = out + (size_t)bidx * C * THW + s0;

  // warp-slice copy geometry: warp wn owns bytes [wn*4096, wn*4096+4096)
  const uint32_t slice_off = (uint32_t)(wn * 4096 + lane * 16);

  // --- kick stage 0 weight copy (own slice) -------------------------------
  {
    const unsigned char* src = g_wimg + slice_off;
    uint32_t dst = smb + SM_WBUF0 + slice_off;
#pragma unroll
    for (int it = 0; it < 8; ++it)
      cp16(dst + it * 512, src + it * 512);
    cp_commit();
  }

  // --- stage gate_w / b1 / b2 ---------------------------------------------
#pragma unroll
  for (int rr = 0; rr < 4; ++rr) {
    int i = rr * NTHR + tid;
    gws[i] = gate_w[i];
    b1s[i] = b1[i];
    b2s[i] = b2[i];
  }
  __syncthreads();

  // --- x staging (fp32->bf16, swizzled) + fp32 gate logit partials --------
  {
    const int t   = tid & 31;
    const int cpg = tid >> 5;  // 0..7
    float l[4] = {0.f, 0.f, 0.f, 0.f};
    const float* gx = xb + t;
#pragma unroll
    for (int it = 0; it < 16; ++it) {
      int c0 = it * 16 + cpg * 2;
      float v0 = __ldg(gx + (size_t)c0 * THW);
      float v1 = __ldg(gx + (size_t)(c0 + 1) * THW);
#pragma unroll
      for (int e = 0; e < 4; ++e)
        l[e] = fmaf(gws[e * 256 + c0], v0, fmaf(gws[e * 256 + c0 + 1], v1, l[e]));
      uint32_t pk = pack_bf2(v0, v1);
      uint32_t off = t * 512 + (((c0 >> 3) ^ (t & 7)) << 4) + (c0 & 7) * 2;
      *reinterpret_cast<uint32_t*>(smraw + SM_XS + off) = pk;
    }
#pragma unroll
    for (int e = 0; e < 4; ++e) sp[cpg * 128 + t * 4 + e] = l[e];
  }
  __syncthreads();

  // --- logits reduce + top-2 softmax --------------------------------------
  if (tid < 32) {
    float l[4];
#pragma unroll
    for (int e = 0; e < 4; ++e) {
      float s = __ldg(gate_b + e);
#pragma unroll
      for (int g = 0; g < 8; ++g) s += sp[g * 128 + tid * 4 + e];
      l[e] = s;
    }
    float v1 = l[0]; int i1 = 0;
    if (l[1] > v1) { v1 = l[1]; i1 = 1; }
    if (l[2] > v1) { v1 = l[2]; i1 = 2; }
    if (l[3] > v1) { v1 = l[3]; i1 = 3; }
    float v2 = -3.402823e38f; int i2 = 0;
#pragma unroll
    for (int e = 0; e < 4; ++e)
      if (e != i1 && l[e] > v2) { v2 = l[e]; i2 = e; }
    float e2  = __expf(v2 - v1);
    float inv = 1.0f / (1.0f + e2);
    wts[tid * 4 + 0] = 0.f; wts[tid * 4 + 1] = 0.f;
    wts[tid * 4 + 2] = 0.f; wts[tid * 4 + 3] = 0.f;
    wts[tid * 4 + i1] = inv;
    wts[tid * 4 + i2] = e2 * inv;
  }
  __syncthreads();  // wts visible; gating overlays (gws/sp in HS) dead

  // --- precompute ldsm addresses (loop-invariant) -------------------------
  uint32_t aofs[8], bofs[8];
  {
    const int r  = lane & 7;
    const int mi = lane >> 3;
#pragma unroll
    for (int mt = 0; mt < 2; ++mt)
#pragma unroll
      for (int kq = 0; kq < 2; ++kq)
#pragma unroll
        for (int ks = 0; ks < 2; ++ks) {
          int row = mt * 16 + (mi & 1) * 8 + r;
          int q   = (kq * 2 + ks) * 2 + (mi >> 1);
          aofs[mt * 4 + kq * 2 + ks] =
              smb + SM_XS + (uint32_t)row * 512 + (uint32_t)((q ^ r) << 4);
        }
#pragma unroll
    for (int nt = 0; nt < 4; ++nt)
#pragma unroll
      for (int kq = 0; kq < 2; ++kq) {
        int kc = kq * 4 + mi;
        bofs[nt * 2 + kq] = (uint32_t)(wn * 32 + nt * 8 + r) * 128 +
                            (uint32_t)((kc ^ r) << 4);
      }
  }

  // --- main loop: warp-autonomous, 4 experts x 8 compile-time phases ------
  float acc1[2][4][4], acc2[2][4][4];
#pragma unroll
  for (int mt = 0; mt < 2; ++mt)
#pragma unroll
    for (int nt = 0; nt < 4; ++nt)
#pragma unroll
      for (int j = 0; j < 4; ++j) acc2[mt][nt][j] = 0.f;

  const unsigned char* gsrc = g_wimg + STAGE_BYTES + slice_off;  // stage 1
#pragma unroll 1
  for (int e = 0; e < E; ++e) {
#pragma unroll
    for (int ph = 0; ph < 8; ++ph) {
      const bool last = (ph == 7) && (e == E - 1);
      if (!last) {  // prefetch own slice of next stage
        uint32_t dst = smb + (((ph + 1) & 1) ? SM_WBUF1 : SM_WBUF0) + slice_off;
#pragma unroll
        for (int it = 0; it < 8; ++it)
          cp16(dst + it * 512, gsrc + it * 512);
        cp_commit();
        gsrc += STAGE_BYTES;
        cp_wait<1>();
      } else {
        cp_wait<0>();
      }
      __syncwarp();

      const uint32_t wbuf = smb + ((ph & 1) ? SM_WBUF1 : SM_WBUF0);

      if (ph < 4) {
        if (ph == 0) {
#pragma unroll
          for (int mt = 0; mt < 2; ++mt)
#pragma unroll
            for (int nt = 0; nt < 4; ++nt)
#pragma unroll
              for (int j = 0; j < 4; ++j) acc1[mt][nt][j] = 0.f;
        }
        run_stage(acc1, aofs, (uint32_t)(ph * 128), bofs, wbuf);
        if (ph == 3) {
          __syncthreads();  // prev expert's HS readers (ph4-7) all done
          // h epilogue: +b1, SiLU, x gate weight, pack bf16 -> hs
#pragma unroll
          for (int mt = 0; mt < 2; ++mt) {
            const int tok1 = mt * 16 + (lane >> 2);
            const int tok2 = tok1 + 8;
            const float wt1 = wts[tok1 * 4 + e];
            const float wt2 = wts[tok2 * 4 + e];
#pragma unroll
            for (int nt = 0; nt < 4; ++nt) {
              int n = wn * 32 + nt * 8 + (lane & 3) * 2;
              float ba = b1s[e * 256 + n], bb = b1s[e * 256 + n + 1];
              float h0 = acc1[mt][nt][0] + ba, h1 = acc1[mt][nt][1] + bb;
              float h2 = acc1[mt][nt][2] + ba, h3 = acc1[mt][nt][3] + bb;
              h0 = h0 * (1.0f / (1.0f + __expf(-h0))) * wt1;
              h1 = h1 * (1.0f / (1.0f + __expf(-h1))) * wt1;
              h2 = h2 * (1.0f / (1.0f + __expf(-h2))) * wt2;
              h3 = h3 * (1.0f / (1.0f + __expf(-h3))) * wt2;
              uint32_t o1 = tok1 * 512 + (((n >> 3) ^ (tok1 & 7)) << 4) + (n & 7) * 2;
              uint32_t o2 = tok2 * 512 + (((n >> 3) ^ (tok2 & 7)) << 4) + (n & 7) * 2;
              *reinterpret_cast<uint32_t*>(smraw + SM_HS + o1) = pack_bf2(h0, h1);
              *reinterpret_cast<uint32_t*>(smraw + SM_HS + o2) = pack_bf2(h2, h3);
            }
          }
        }
      } else {
        if (ph == 4) __syncthreads();  // all HS writes visible
        run_stage(acc2, aofs, (uint32_t)(16384 + (ph - 4) * 128), bofs, wbuf);
      }
    }
  }
  __syncthreads();  // all warps done before d2s overlays weight buffers

  // --- final epilogue: acc2 -> smem (coalescing relay) -> global ----------
  float* d2s = reinterpret_cast<float*>(smraw);  // overlays weight buffers
  {
    const int tok1 = lane >> 2;
    const int tok2 = tok1 + 8;
#pragma unroll
    for (int mt = 0; mt < 2; ++mt) {
      const int t1 = mt * 16 + tok1;
      const int t2 = mt * 16 + tok2;
#pragma unroll
      for (int nt = 0; nt < 4; ++nt) {
        int n = wn * 32 + nt * 8 + (lane & 3) * 2;
        *reinterpret_cast<float2*>(d2s + t1 * 258 + n) =
            make_float2(acc2[mt][nt][0], acc2[mt][nt][1]);
        *reinterpret_cast<float2*>(d2s + t2 * 258 + n) =
            make_float2(acc2[mt][nt][2], acc2[mt][nt][3]);
      }
    }
  }
  __syncthreads();
  {
    const int t  = tid & 31;
    const int cg = tid >> 5;   // 0..7
    const float w0 = wts[t * 4 + 0], w1w = wts[t * 4 + 1];
    const float w2w = wts[t * 4 + 2], w3 = wts[t * 4 + 3];
#pragma unroll 4
    for (int i = 0; i < 32; ++i) {
      int ch = i * 8 + cg;
      float v = d2s[t * 258 + ch]
              + w0  * b2s[ch]       + w1w * b2s[256 + ch]
              + w2w * b2s[512 + ch] + w3  * b2s[768 + ch]
              + __ldg(xb + (size_t)ch * THW + t);
      ob[(size_t)ch * THW + t] = v;
    }
  }
}

// ---------------------------------------------------------------------------
extern "C" void kernel_launch(void* const* d_in, const int* in_sizes, int n_in,
                              void* d_out, int out_size) {
  const float* x      = (const float*)d_in[0];
  const float* gate_w = (const float*)d_in[1];
  const float* gate_b = (const float*)d_in[2];
  const float* w1     = (const float*)d_in[3];
  const float* b1     = (const float*)d_in[4];
  const float* w2     = (const float*)d_in[5];
  const float* b2     = (const float*)d_in[6];
  float* out          = (float*)d_out;
  (void)in_sizes; (void)n_in; (void)out_size;

  prep_weights<<<256, 256>>>(w1, w2);

  cudaFuncSetAttribute(moe_mma_kernel,
                       cudaFuncAttributeMaxDynamicSharedMemorySize, SM_TOTAL);
  moe_mma_kernel<<<NCTA, NTHR, SM_TOTAL>>>(x, gate_w, gate_b, b1, b2, out);
}